// round 10
// baseline (speedup 1.0000x reference)
#include <cuda_runtime.h>
#include <cuda_fp16.h>
#include <cstdint>

#define BATCH 4
#define CIN   256
#define HC    128
#define NPIX  4096

// ---------------- scratch (static __device__, no allocations) ----------------
__device__ __half g_th_hi[BATCH * NPIX * HC];  // theta [b][n][d] hi
__device__ __half g_th_lo[BATCH * NPIX * HC];  // theta lo
__device__ __half g_ph_hi[BATCH * NPIX * HC];  // phi   [b][m][d] hi
__device__ __half g_ph_lo[BATCH * NPIX * HC];  // phi   lo
__device__ __half g_gh  [BATCH * HC * NPIX];   // g     [b][d][m] fp16
__device__ float  g_y   [BATCH * HC * NPIX];   // y     [b][d][n] fp32

// ---------------- helpers ----------------------------------------------------
__device__ __forceinline__ uint32_t smem_to_u32(const void* p) {
    uint32_t a;
    asm("{ .reg .u64 t; cvta.to.shared.u64 t, %1; cvt.u32.u64 %0, t; }" : "=r"(a) : "l"(p));
    return a;
}

#define LDSM4(r0, r1, r2, r3, addr) \
    asm volatile("ldmatrix.sync.aligned.m8n8.x4.shared.b16 {%0,%1,%2,%3}, [%4];" \
                 : "=r"(r0), "=r"(r1), "=r"(r2), "=r"(r3) : "r"(addr))

#define CP_ASYNC16(dst, src) \
    asm volatile("cp.async.cg.shared.global [%0], [%1], 16;" :: "r"(dst), "l"(src))
#define CP_COMMIT()  asm volatile("cp.async.commit_group;" ::: "memory")
#define CP_WAIT0()   asm volatile("cp.async.wait_group 0;" ::: "memory")

__device__ __forceinline__ void mma16816(float c[4], const uint32_t a[4],
                                         uint32_t b0, uint32_t b1) {
    asm volatile("mma.sync.aligned.m16n8k16.row.col.f32.f16.f16.f32 "
                 "{%0,%1,%2,%3}, {%4,%5,%6,%7}, {%8,%9}, {%0,%1,%2,%3};"
                 : "+f"(c[0]), "+f"(c[1]), "+f"(c[2]), "+f"(c[3])
                 : "r"(a[0]), "r"(a[1]), "r"(a[2]), "r"(a[3]), "r"(b0), "r"(b1));
}

__device__ __forceinline__ uint32_t pack_h2(float lo, float hi) {
    uint32_t u;
    asm("cvt.rn.f16x2.f32 %0, %1, %2;" : "=r"(u) : "f"(hi), "f"(lo));
    return u;
}

// fast exp on the FMA pipe
__device__ __forceinline__ float fexp(float x) {
    float t = x * 1.4426950408889634f;
    t = fminf(fmaxf(t, -125.0f), 125.0f);
    float fi = rintf(t);
    float f  = t - fi;
    float p  = 1.3333558146428443e-3f;
    p = fmaf(p, f, 9.618129107628477e-3f);
    p = fmaf(p, f, 5.550410866482158e-2f);
    p = fmaf(p, f, 2.402265069591007e-1f);
    p = fmaf(p, f, 6.931471805599453e-1f);
    p = fmaf(p, f, 1.0f);
    return __int_as_float(__float_as_int(p) + ((int)fi << 23));
}

// swizzles: 256B rows (16 chunks) and 128B rows (8 chunks)
#define SWZ(r, c)  ((uint32_t)((r) * 256 + (((c) ^ ((r) & 7)) << 4)))
#define SWZP(r, c) ((uint32_t)((r) * 128 + (((c) ^ ((r) & 7)) << 4)))

// ---------------- projection: out[o][n] = sum_c w[o][c] x[c][n] + b[o] ------
__global__ __launch_bounds__(256) void proj_kernel(
    const float* __restrict__ x, const float* __restrict__ w,
    const float* __restrict__ bias, int which)
{
    __shared__ float wT[16][132];
    __shared__ float xs[16][128];
    const int tid = threadIdx.x;
    const int ty = tid >> 4, tx = tid & 15;
    const int wp = tid >> 5, lane = tid & 31;
    const int n0 = blockIdx.x * 128;
    const int b  = blockIdx.y;
    const float* xb = x + (size_t)b * CIN * NPIX;

    float acc[8][8];
#pragma unroll
    for (int i = 0; i < 8; i++)
#pragma unroll
        for (int j = 0; j < 8; j++) acc[i][j] = 0.0f;

    for (int kc = 0; kc < CIN; kc += 16) {
        __syncthreads();
#pragma unroll
        for (int s = 0; s < 8; s++) {
            int li = s * 256 + tid;
            int o = li >> 4, cc = li & 15;
            wT[cc][o] = w[o * CIN + kc + cc];
        }
#pragma unroll
        for (int r = wp; r < 16; r += 8)
            *(float4*)&xs[r][lane * 4] =
                *(const float4*)&xb[(size_t)(kc + r) * NPIX + n0 + lane * 4];
        __syncthreads();
#pragma unroll
        for (int cc = 0; cc < 16; cc++) {
            float a[8], bb[8];
            *(float4*)&a[0]  = *(float4*)&wT[cc][ty * 8];
            *(float4*)&a[4]  = *(float4*)&wT[cc][ty * 8 + 4];
            *(float4*)&bb[0] = *(float4*)&xs[cc][tx * 8];
            *(float4*)&bb[4] = *(float4*)&xs[cc][tx * 8 + 4];
#pragma unroll
            for (int i = 0; i < 8; i++)
#pragma unroll
                for (int j = 0; j < 8; j++) acc[i][j] = fmaf(a[i], bb[j], acc[i][j]);
        }
    }

    float bv[8];
    *(float4*)&bv[0] = *(const float4*)&bias[ty * 8];
    *(float4*)&bv[4] = *(const float4*)&bias[ty * 8 + 4];

    if (which < 2) {
        __half* oh = (which == 0 ? g_th_hi : g_ph_hi) + (size_t)b * NPIX * HC;
        __half* ol = (which == 0 ? g_th_lo : g_ph_lo) + (size_t)b * NPIX * HC;
#pragma unroll
        for (int j = 0; j < 8; j++) {
            int n = n0 + tx * 8 + j;
            __half hs[8], ls[8];
#pragma unroll
            for (int i = 0; i < 8; i++) {
                float v = acc[i][j] + bv[i];
                __half h = __float2half_rn(v);
                hs[i] = h;
                ls[i] = __float2half_rn(v - __half2float(h));
            }
            *(uint4*)&oh[(size_t)n * HC + ty * 8] = *(uint4*)hs;
            *(uint4*)&ol[(size_t)n * HC + ty * 8] = *(uint4*)ls;
        }
    } else {
        __half* ob = g_gh + (size_t)b * HC * NPIX;
#pragma unroll
        for (int i = 0; i < 8; i++) {
            int d = ty * 8 + i;
            __half hv[8];
#pragma unroll
            for (int q = 0; q < 8; q++) hv[q] = __float2half_rn(acc[i][q] + bv[i]);
            *(uint4*)&ob[(size_t)d * NPIX + n0 + tx * 8] = *(uint4*)hv;
        }
    }
}

// ---------------- smem layout for pipelined flash -----------------------------
#define TH_OFF  0u
#define TL_OFF  32768u
#define PH0H    65536u
#define PH0L    81920u
#define PH1H    98304u
#define PH1L    114688u
#define G0_OFF  131072u
#define G1_OFF  147456u
#define PP0_OFF 163840u
#define PP1_OFF 180224u
#define HM_OFF  196608u
#define ES_OFF  196608u
#define OSM_OFF 65536u
#define FLASH_SMEM (198656)

// stage a [128 rows][256B] tile (theta), row stride rs halves
__device__ __forceinline__ void stage_full_256(uint32_t dst, const __half* __restrict__ src,
                                               int tid) {
#pragma unroll
    for (int i = 0; i < 8; i++) {
        int id = tid + i * 256;
        int r = id >> 4, c = id & 15;
        CP_ASYNC16(dst + SWZ(r, c), src + (size_t)r * HC + c * 8);
    }
}
// stage a [64 rows][256B] tile (phi half), row stride HC
__device__ __forceinline__ void stage_half_256(uint32_t dst, const __half* __restrict__ src,
                                               int tid) {
#pragma unroll
    for (int i = 0; i < 4; i++) {
        int id = tid + i * 256;
        int r = id >> 4, c = id & 15;
        CP_ASYNC16(dst + SWZ(r, c), src + (size_t)r * HC + c * 8);
    }
}
// stage a [128 rows][128B] tile (g half), row stride NPIX
__device__ __forceinline__ void stage_half_128(uint32_t dst, const __half* __restrict__ src,
                                               int tid) {
#pragma unroll
    for (int i = 0; i < 4; i++) {
        int id = tid + i * 256;
        int r = id >> 3, c = id & 7;
        CP_ASYNC16(dst + SWZP(r, c), src + (size_t)r * NPIX + c * 8);
    }
}

// body macro: H = half index (0..63), PAR = H&1 (literal), SW write sacc, SR read sacc
#define FLASH_BODY(H, PAR, SW, SR) do {                                        \
    if ((H) + 1 < 64) {                                                        \
        const __half* ps = PhH + (size_t)((H) + 1) * 64 * HC;                  \
        const __half* pl = PhL + (size_t)((H) + 1) * 64 * HC;                  \
        stage_half_256(sb + ((PAR) ? PH0H : PH1H), ps, tid);                   \
        stage_half_256(sb + ((PAR) ? PH0L : PH1L), pl, tid);                   \
    }                                                                          \
    stage_half_128(sb + ((PAR) ? G1_OFF : G0_OFF), Gm + (size_t)(H) * 64, tid);\
    CP_COMMIT();                                                               \
    {   /* step1: MMA1(H) interleaved with epi(H-1) */                         \
        _Pragma("unroll")                                                      \
        for (int tz = 0; tz < 2; tz++)                                         \
            _Pragma("unroll")                                                  \
            for (int jz = 0; jz < 4; jz++)                                     \
                _Pragma("unroll")                                              \
                for (int qz = 0; qz < 4; qz++) SW[tz][jz][qz] = 0.0f;          \
        const uint32_t phh = sb + ((PAR) ? PH1H : PH0H);                       \
        const uint32_t phl = sb + ((PAR) ? PH1L : PH0L);                       \
        const uint32_t ppb = ((PAR) ? PP0_OFF : PP1_OFF);                      \
        _Pragma("unroll")                                                      \
        for (int kk = 0; kk < 8; kk++) {                                       \
            uint32_t ah[2][4], al[2][4];                                       \
            _Pragma("unroll")                                                  \
            for (int t = 0; t < 2; t++) {                                      \
                int r = wy * 32 + t * 16 + arow;                               \
                int c = 2 * kk + acol;                                         \
                LDSM4(ah[t][0], ah[t][1], ah[t][2], ah[t][3], sb + TH_OFF + SWZ(r, c)); \
                LDSM4(al[t][0], al[t][1], al[t][2], al[t][3], sb + TL_OFF + SWZ(r, c)); \
            }                                                                  \
            _Pragma("unroll")                                                  \
            for (int p = 0; p < 2; p++) {                                      \
                int r = wx * 32 + p * 16 + brow;                               \
                int c = 2 * kk + bcol;                                         \
                uint32_t bh0, bh1, bh2, bh3, bl0, bl1, bl2, bl3;               \
                LDSM4(bh0, bh1, bh2, bh3, phh + SWZ(r, c));                    \
                LDSM4(bl0, bl1, bl2, bl3, phl + SWZ(r, c));                    \
                _Pragma("unroll")                                              \
                for (int t = 0; t < 2; t++) {                                  \
                    mma16816(SW[t][2 * p],     ah[t], bh0, bh1);               \
                    mma16816(SW[t][2 * p],     ah[t], bl0, bl1);               \
                    mma16816(SW[t][2 * p],     al[t], bh0, bh1);               \
                    mma16816(SW[t][2 * p + 1], ah[t], bh2, bh3);               \
                    mma16816(SW[t][2 * p + 1], ah[t], bl2, bl3);               \
                    mma16816(SW[t][2 * p + 1], al[t], bh2, bh3);               \
                }                                                              \
            }                                                                  \
            if ((H) > 0) {  /* epi chunk kk: (t,j) = (kk>>2, kk&3) */          \
                const int te = kk >> 2, je = kk & 3;                           \
                float e0 = fexp(SR[te][je][0] - mcur[te * 2]);                 \
                float e1 = fexp(SR[te][je][1] - mcur[te * 2]);                 \
                float e2 = fexp(SR[te][je][2] - mcur[te * 2 + 1]);             \
                float e3 = fexp(SR[te][je][3] - mcur[te * 2 + 1]);             \
                uint32_t p01 = pack_h2(e0, e1);                                \
                uint32_t p23 = pack_h2(e2, e3);                                \
                __half2 h01 = *reinterpret_cast<__half2*>(&p01);               \
                __half2 h23 = *reinterpret_cast<__half2*>(&p23);               \
                esp[te * 2 + 0] += __low2float(h01) + __high2float(h01);       \
                esp[te * 2 + 1] += __low2float(h23) + __high2float(h23);       \
                int row0 = wy * 32 + te * 16 + (lane >> 2);                    \
                int cch  = wx * 4 + je;                                        \
                *(uint32_t*)(smem + ppb + SWZP(row0, cch) + (lane & 3) * 4)     = p01; \
                *(uint32_t*)(smem + ppb + SWZP(row0 + 8, cch) + (lane & 3) * 4) = p23; \
            }                                                                  \
        }                                                                      \
        /* row max of SW -> HM[PAR] */                                         \
        float mt[4] = {-1e30f, -1e30f, -1e30f, -1e30f};                        \
        _Pragma("unroll")                                                      \
        for (int t = 0; t < 2; t++)                                            \
            _Pragma("unroll")                                                  \
            for (int j = 0; j < 4; j++) {                                      \
                mt[t * 2 + 0] = fmaxf(mt[t * 2 + 0], fmaxf(SW[t][j][0], SW[t][j][1])); \
                mt[t * 2 + 1] = fmaxf(mt[t * 2 + 1], fmaxf(SW[t][j][2], SW[t][j][3])); \
            }                                                                  \
        _Pragma("unroll")                                                      \
        for (int q = 0; q < 4; q++) {                                          \
            mt[q] = fmaxf(mt[q], __shfl_xor_sync(0xFFFFFFFFu, mt[q], 1));      \
            mt[q] = fmaxf(mt[q], __shfl_xor_sync(0xFFFFFFFFu, mt[q], 2));      \
        }                                                                      \
        float* HMp = (float*)(smem + HM_OFF + (PAR) * 1024);                   \
        if ((lane & 3) == 0) {                                                 \
            _Pragma("unroll")                                                  \
            for (int t = 0; t < 2; t++)                                        \
                _Pragma("unroll")                                              \
                for (int h2 = 0; h2 < 2; h2++)                                 \
                    HMp[wx * 128 + wy * 32 + t * 16 + h2 * 8 + (lane >> 2)] = mt[t * 2 + h2]; \
        }                                                                      \
    }                                                                          \
    __syncthreads();                                                           \
    if ((H) > 0) {  /* MMA2(H-1): PP buffer of this parity, g of other parity */ \
        const uint32_t ppb2 = sb + ((PAR) ? PP0_OFF : PP1_OFF);                \
        const uint32_t gb   = sb + ((PAR) ? G0_OFF  : G1_OFF);                 \
        _Pragma("unroll")                                                      \
        for (int kk2 = 0; kk2 < 4; kk2++) {                                    \
            uint32_t ap[2][4];                                                 \
            _Pragma("unroll")                                                  \
            for (int t = 0; t < 2; t++) {                                      \
                int r = wy * 32 + t * 16 + arow;                               \
                LDSM4(ap[t][0], ap[t][1], ap[t][2], ap[t][3],                  \
                      ppb2 + SWZP(r, 2 * kk2 + acol));                         \
            }                                                                  \
            _Pragma("unroll")                                                  \
            for (int p = 0; p < 4; p++) {                                      \
                int r = wx * 64 + p * 16 + brow;                               \
                uint32_t bg0, bg1, bg2, bg3;                                   \
                LDSM4(bg0, bg1, bg2, bg3, gb + SWZP(r, 2 * kk2 + bcol));       \
                _Pragma("unroll")                                              \
                for (int t = 0; t < 2; t++) {                                  \
                    mma16816(oacc[t][2 * p],     ap[t], bg0, bg1);             \
                    mma16816(oacc[t][2 * p + 1], ap[t], bg2, bg3);             \
                }                                                              \
            }                                                                  \
        }                                                                      \
    }                                                                          \
    {   /* rescale(H) from HM[PAR] */                                          \
        float* HMp = (float*)(smem + HM_OFF + (PAR) * 1024);                   \
        float scv[4];                                                          \
        _Pragma("unroll")                                                      \
        for (int t = 0; t < 2; t++)                                            \
            _Pragma("unroll")                                                  \
            for (int h2 = 0; h2 < 2; h2++) {                                   \
                int q = t * 2 + h2;                                            \
                int row = wy * 32 + t * 16 + h2 * 8 + (lane >> 2);             \
                float tm = fmaxf(HMp[row], HMp[128 + row]);                    \
                float Mn = fmaxf(mrun[q], tm);                                 \
                scv[q] = fexp(mrun[q] - Mn);                                   \
                mrun[q] = Mn; mcur[q] = Mn;                                    \
                esp[q] *= scv[q];                                              \
            }                                                                  \
        _Pragma("unroll")                                                      \
        for (int t = 0; t < 2; t++)                                            \
            _Pragma("unroll")                                                  \
            for (int j = 0; j < 8; j++) {                                      \
                oacc[t][j][0] *= scv[t * 2];     oacc[t][j][1] *= scv[t * 2];  \
                oacc[t][j][2] *= scv[t * 2 + 1]; oacc[t][j][3] *= scv[t * 2 + 1]; \
            }                                                                  \
    }                                                                          \
    CP_WAIT0();                                                                \
    __syncthreads();                                                           \
} while (0)

__global__ __launch_bounds__(256, 1) void flash_mma_kernel()
{
    extern __shared__ char smem[];
    const uint32_t sb = smem_to_u32(smem);
    const int tid  = threadIdx.x;
    const int wid  = tid >> 5, lane = tid & 31;
    const int wy   = wid >> 1;          // n band (0..3)
    const int wx   = wid & 1;           // m / d half (0..1)
    const int n0   = blockIdx.x * 128;
    const int b    = blockIdx.y;

    const __half* ThH = g_th_hi + ((size_t)b * NPIX + n0) * HC;
    const __half* ThL = g_th_lo + ((size_t)b * NPIX + n0) * HC;
    const __half* PhH = g_ph_hi + (size_t)b * NPIX * HC;
    const __half* PhL = g_ph_lo + (size_t)b * NPIX * HC;
    const __half* Gm  = g_gh    + (size_t)b * HC * NPIX;
    float*        Yb  = g_y     + (size_t)b * HC * NPIX;

    // prologue: theta (resident) + phi(0)
    stage_full_256(sb + TH_OFF, ThH, tid);
    stage_full_256(sb + TL_OFF, ThL, tid);
    stage_half_256(sb + PH0H, PhH, tid);
    stage_half_256(sb + PH0L, PhL, tid);
    CP_COMMIT();
    CP_WAIT0();
    __syncthreads();

    float oacc[2][8][4];
#pragma unroll
    for (int t = 0; t < 2; t++)
#pragma unroll
        for (int j = 0; j < 8; j++)
#pragma unroll
            for (int q = 0; q < 4; q++) oacc[t][j][q] = 0.0f;
    float esp[4]  = {0.0f, 0.0f, 0.0f, 0.0f};
    float mrun[4] = {-1e30f, -1e30f, -1e30f, -1e30f};
    float mcur[4] = {-1e30f, -1e30f, -1e30f, -1e30f};
    float sacc0[2][4][4], sacc1[2][4][4];

    const int arow = (lane & 7) + ((lane >> 3) & 1) * 8;
    const int acol = lane >> 4;
    const int brow = (lane & 7) + (lane >> 4) * 8;
    const int bcol = (lane >> 3) & 1;

#pragma unroll 1
    for (int h = 0; h < 64; h += 2) {
        FLASH_BODY(h,     0, sacc0, sacc1);
        FLASH_BODY(h + 1, 1, sacc1, sacc0);
    }

    // tail body (h = 64): epi(63) [reads sacc1, PP1], barrier, MMA2(63)
    {
        const uint32_t ppb = PP1_OFF;
#pragma unroll
        for (int kk = 0; kk < 8; kk++) {
            const int te = kk >> 2, je = kk & 3;
            float e0 = fexp(sacc1[te][je][0] - mcur[te * 2]);
            float e1 = fexp(sacc1[te][je][1] - mcur[te * 2]);
            float e2 = fexp(sacc1[te][je][2] - mcur[te * 2 + 1]);
            float e3 = fexp(sacc1[te][je][3] - mcur[te * 2 + 1]);
            uint32_t p01 = pack_h2(e0, e1);
            uint32_t p23 = pack_h2(e2, e3);
            __half2 h01 = *reinterpret_cast<__half2*>(&p01);
            __half2 h23 = *reinterpret_cast<__half2*>(&p23);
            esp[te * 2 + 0] += __low2float(h01) + __high2float(h01);
            esp[te * 2 + 1] += __low2float(h23) + __high2float(h23);
            int row0 = wy * 32 + te * 16 + (lane >> 2);
            int cch  = wx * 4 + je;
            *(uint32_t*)(smem + ppb + SWZP(row0, cch) + (lane & 3) * 4)     = p01;
            *(uint32_t*)(smem + ppb + SWZP(row0 + 8, cch) + (lane & 3) * 4) = p23;
        }
        __syncthreads();
        const uint32_t ppb2 = sb + PP1_OFF;
        const uint32_t gb   = sb + G1_OFF;
#pragma unroll
        for (int kk2 = 0; kk2 < 4; kk2++) {
            uint32_t ap[2][4];
#pragma unroll
            for (int t = 0; t < 2; t++) {
                int r = wy * 32 + t * 16 + arow;
                LDSM4(ap[t][0], ap[t][1], ap[t][2], ap[t][3],
                      ppb2 + SWZP(r, 2 * kk2 + acol));
            }
#pragma unroll
            for (int p = 0; p < 4; p++) {
                int r = wx * 64 + p * 16 + brow;
                uint32_t bg0, bg1, bg2, bg3;
                LDSM4(bg0, bg1, bg2, bg3, gb + SWZP(r, 2 * kk2 + bcol));
#pragma unroll
                for (int t = 0; t < 2; t++) {
                    mma16816(oacc[t][2 * p],     ap[t], bg0, bg1);
                    mma16816(oacc[t][2 * p + 1], ap[t], bg2, bg3);
                }
            }
        }
        __syncthreads();
    }

    // ---- softmax denominators --------------------------------------------
    float* ES = (float*)(smem + ES_OFF);
#pragma unroll
    for (int q = 0; q < 4; q++) {
        float v = esp[q];
        v += __shfl_xor_sync(0xFFFFFFFFu, v, 1);
        v += __shfl_xor_sync(0xFFFFFFFFu, v, 2);
        if ((lane & 3) == 0)
            ES[wx * 128 + wy * 32 + (q >> 1) * 16 + (q & 1) * 8 + (lane >> 2)] = v;
    }
    __syncthreads();

    // ---- normalize, stage O[n][d] in smem --------------------------------
    float* OSM = (float*)(smem + OSM_OFF);   // [128][132]
#pragma unroll
    for (int t = 0; t < 2; t++) {
        int row0 = wy * 32 + t * 16 + (lane >> 2);
        float rv0 = 1.0f / (ES[row0] + ES[128 + row0]);
        float rv1 = 1.0f / (ES[row0 + 8] + ES[128 + row0 + 8]);
#pragma unroll
        for (int j = 0; j < 8; j++) {
            int d = wx * 64 + j * 8 + (lane & 3) * 2;
            OSM[row0 * 132 + d]           = oacc[t][j][0] * rv0;
            OSM[row0 * 132 + d + 1]       = oacc[t][j][1] * rv0;
            OSM[(row0 + 8) * 132 + d]     = oacc[t][j][2] * rv1;
            OSM[(row0 + 8) * 132 + d + 1] = oacc[t][j][3] * rv1;
        }
    }
    __syncthreads();

    // ---- coalesced y write: y[b][d][n] -----------------------------------
#pragma unroll
    for (int i = 0; i < 16; i++) {
        int id = tid + i * 256;
        int d = id >> 5, nc = (id & 31) * 4;
        float4 v;
        v.x = OSM[(nc + 0) * 132 + d];
        v.y = OSM[(nc + 1) * 132 + d];
        v.z = OSM[(nc + 2) * 132 + d];
        v.w = OSM[(nc + 3) * 132 + d];
        *(float4*)&Yb[(size_t)d * NPIX + n0 + nc] = v;
    }
}

// ---------------- final: z[c][n] = sum_d w_w[c][d] y[d][n] + b_w[c] + x ------
__global__ __launch_bounds__(256) void final_kernel(
    const float* __restrict__ ww, const float* __restrict__ bw,
    const float* __restrict__ x, float* __restrict__ out)
{
    __shared__ float wTs[16][132];
    __shared__ float ys[16][128];
    const int tid = threadIdx.x;
    const int ty = tid >> 4, tx = tid & 15;
    const int wp = tid >> 5, lane = tid & 31;
    const int n0 = blockIdx.x * 128;
    const int c0 = blockIdx.y * 128;
    const int b  = blockIdx.z;
    const float* Yb = g_y + (size_t)b * HC * NPIX;

    float acc[8][8];
#pragma unroll
    for (int i = 0; i < 8; i++)
#pragma unroll
        for (int j = 0; j < 8; j++) acc[i][j] = 0.0f;

    for (int kc = 0; kc < HC; kc += 16) {
        __syncthreads();
#pragma unroll
        for (int s = 0; s < 8; s++) {
            int li = s * 256 + tid;
            int c = li >> 4, dd = li & 15;
            wTs[dd][c] = ww[(size_t)(c0 + c) * HC + kc + dd];
        }
#pragma unroll
        for (int r = wp; r < 16; r += 8)
            *(float4*)&ys[r][lane * 4] =
                *(const float4*)&Yb[(size_t)(kc + r) * NPIX + n0 + lane * 4];
        __syncthreads();
#pragma unroll
        for (int dd = 0; dd < 16; dd++) {
            float a[8], bb[8];
            *(float4*)&a[0]  = *(float4*)&wTs[dd][ty * 8];
            *(float4*)&a[4]  = *(float4*)&wTs[dd][ty * 8 + 4];
            *(float4*)&bb[0] = *(float4*)&ys[dd][tx * 8];
            *(float4*)&bb[4] = *(float4*)&ys[dd][tx * 8 + 4];
#pragma unroll
            for (int i = 0; i < 8; i++)
#pragma unroll
                for (int j = 0; j < 8; j++) acc[i][j] = fmaf(a[i], bb[j], acc[i][j]);
        }
    }

    const float* xb = x + ((size_t)b * CIN + c0) * NPIX;
    float* ob = out + ((size_t)b * CIN + c0) * NPIX;
#pragma unroll
    for (int i = 0; i < 8; i++) {
        int c = ty * 8 + i;
        float bi = bw[c0 + c];
        float4 xv0 = *(const float4*)&xb[(size_t)c * NPIX + n0 + tx * 8];
        float4 xv1 = *(const float4*)&xb[(size_t)c * NPIX + n0 + tx * 8 + 4];
        float4 v0, v1;
        v0.x = acc[i][0] + bi + xv0.x; v0.y = acc[i][1] + bi + xv0.y;
        v0.z = acc[i][2] + bi + xv0.z; v0.w = acc[i][3] + bi + xv0.w;
        v1.x = acc[i][4] + bi + xv1.x; v1.y = acc[i][5] + bi + xv1.y;
        v1.z = acc[i][6] + bi + xv1.z; v1.w = acc[i][7] + bi + xv1.w;
        *(float4*)&ob[(size_t)c * NPIX + n0 + tx * 8]     = v0;
        *(float4*)&ob[(size_t)c * NPIX + n0 + tx * 8 + 4] = v1;
    }
}

// ---------------- launch -----------------------------------------------------
extern "C" void kernel_launch(void* const* d_in, const int* in_sizes, int n_in,
                              void* d_out, int out_size)
{
    const float* x       = (const float*)d_in[0];
    const float* w_theta = (const float*)d_in[1];
    const float* b_theta = (const float*)d_in[2];
    const float* w_phi   = (const float*)d_in[3];
    const float* b_phi   = (const float*)d_in[4];
    const float* w_g     = (const float*)d_in[5];
    const float* b_g     = (const float*)d_in[6];
    const float* w_w     = (const float*)d_in[7];
    const float* b_w     = (const float*)d_in[8];
    float* out = (float*)d_out;

    cudaFuncSetAttribute(flash_mma_kernel,
                         cudaFuncAttributeMaxDynamicSharedMemorySize, FLASH_SMEM);

    dim3 g1(32, BATCH);
    proj_kernel<<<g1, 256>>>(x, w_theta, b_theta, 0);
    proj_kernel<<<g1, 256>>>(x, w_phi,   b_phi,   1);
    proj_kernel<<<g1, 256>>>(x, w_g,     b_g,     2);
    flash_mma_kernel<<<g1, 256, FLASH_SMEM>>>();
    final_kernel<<<dim3(32, 2, BATCH), 256>>>(w_w, b_w, x, out);
}

// round 11
// speedup vs baseline: 1.1239x; 1.1239x over previous
#include <cuda_runtime.h>
#include <cuda_fp16.h>
#include <cstdint>

#define BATCH 4
#define CIN   256
#define HC    128
#define NPIX  4096

// ---------------- scratch (static __device__, no allocations) ----------------
__device__ __half g_th_hi[BATCH * NPIX * HC];  // theta [b][n][d] hi
__device__ __half g_th_lo[BATCH * NPIX * HC];  // theta lo
__device__ __half g_ph_hi[BATCH * NPIX * HC];  // phi   [b][m][d] hi
__device__ __half g_gh  [BATCH * HC * NPIX];   // g     [b][d][m] fp16
__device__ float  g_y   [BATCH * HC * NPIX];   // y     [b][d][n] fp32

// ---------------- helpers ----------------------------------------------------
__device__ __forceinline__ uint32_t smem_to_u32(const void* p) {
    uint32_t a;
    asm("{ .reg .u64 t; cvta.to.shared.u64 t, %1; cvt.u32.u64 %0, t; }" : "=r"(a) : "l"(p));
    return a;
}

#define LDSM4(r0, r1, r2, r3, addr) \
    asm volatile("ldmatrix.sync.aligned.m8n8.x4.shared.b16 {%0,%1,%2,%3}, [%4];" \
                 : "=r"(r0), "=r"(r1), "=r"(r2), "=r"(r3) : "r"(addr))

#define CP_ASYNC16(dst, src) \
    asm volatile("cp.async.cg.shared.global [%0], [%1], 16;" :: "r"(dst), "l"(src))
#define CP_COMMIT()  asm volatile("cp.async.commit_group;" ::: "memory")
#define CP_WAIT0()   asm volatile("cp.async.wait_group 0;" ::: "memory")

__device__ __forceinline__ void mma16816(float c[4], const uint32_t a[4],
                                         uint32_t b0, uint32_t b1) {
    asm volatile("mma.sync.aligned.m16n8k16.row.col.f32.f16.f16.f32 "
                 "{%0,%1,%2,%3}, {%4,%5,%6,%7}, {%8,%9}, {%0,%1,%2,%3};"
                 : "+f"(c[0]), "+f"(c[1]), "+f"(c[2]), "+f"(c[3])
                 : "r"(a[0]), "r"(a[1]), "r"(a[2]), "r"(a[3]), "r"(b0), "r"(b1));
}

__device__ __forceinline__ uint32_t pack_h2(float lo, float hi) {
    uint32_t u;
    asm("cvt.rn.f16x2.f32 %0, %1, %2;" : "=r"(u) : "f"(hi), "f"(lo));
    return u;
}

// fast exp on the FMA pipe
__device__ __forceinline__ float fexp(float x) {
    float t = x * 1.4426950408889634f;
    t = fminf(fmaxf(t, -125.0f), 125.0f);
    float fi = rintf(t);
    float f  = t - fi;
    float p  = 1.3333558146428443e-3f;
    p = fmaf(p, f, 9.618129107628477e-3f);
    p = fmaf(p, f, 5.550410866482158e-2f);
    p = fmaf(p, f, 2.402265069591007e-1f);
    p = fmaf(p, f, 6.931471805599453e-1f);
    p = fmaf(p, f, 1.0f);
    return __int_as_float(__float_as_int(p) + ((int)fi << 23));
}

// swizzles: 256B rows (16 chunks) and 128B rows (8 chunks)
#define SWZ(r, c)  ((uint32_t)((r) * 256 + (((c) ^ ((r) & 7)) << 4)))
#define SWZP(r, c) ((uint32_t)((r) * 128 + (((c) ^ ((r) & 7)) << 4)))

// ---------------- projection: out[o][n] = sum_c w[o][c] x[c][n] + b[o] ------
// which: 0 theta->[n][d] hi+lo, 1 phi->[m][d] hi only, 2 g->[d][m] fp16
__global__ __launch_bounds__(256) void proj_kernel(
    const float* __restrict__ x, const float* __restrict__ w,
    const float* __restrict__ bias, int which)
{
    __shared__ float wT[16][132];
    __shared__ float xs[16][128];
    const int tid = threadIdx.x;
    const int ty = tid >> 4, tx = tid & 15;
    const int wp = tid >> 5, lane = tid & 31;
    const int n0 = blockIdx.x * 128;
    const int b  = blockIdx.y;
    const float* xb = x + (size_t)b * CIN * NPIX;

    float acc[8][8];
#pragma unroll
    for (int i = 0; i < 8; i++)
#pragma unroll
        for (int j = 0; j < 8; j++) acc[i][j] = 0.0f;

    for (int kc = 0; kc < CIN; kc += 16) {
        __syncthreads();
#pragma unroll
        for (int s = 0; s < 8; s++) {
            int li = s * 256 + tid;
            int o = li >> 4, cc = li & 15;
            wT[cc][o] = w[o * CIN + kc + cc];
        }
#pragma unroll
        for (int r = wp; r < 16; r += 8)
            *(float4*)&xs[r][lane * 4] =
                *(const float4*)&xb[(size_t)(kc + r) * NPIX + n0 + lane * 4];
        __syncthreads();
#pragma unroll
        for (int cc = 0; cc < 16; cc++) {
            float a[8], bb[8];
            *(float4*)&a[0]  = *(float4*)&wT[cc][ty * 8];
            *(float4*)&a[4]  = *(float4*)&wT[cc][ty * 8 + 4];
            *(float4*)&bb[0] = *(float4*)&xs[cc][tx * 8];
            *(float4*)&bb[4] = *(float4*)&xs[cc][tx * 8 + 4];
#pragma unroll
            for (int i = 0; i < 8; i++)
#pragma unroll
                for (int j = 0; j < 8; j++) acc[i][j] = fmaf(a[i], bb[j], acc[i][j]);
        }
    }

    float bv[8];
    *(float4*)&bv[0] = *(const float4*)&bias[ty * 8];
    *(float4*)&bv[4] = *(const float4*)&bias[ty * 8 + 4];

    if (which < 2) {
        __half* oh = (which == 0 ? g_th_hi : g_ph_hi) + (size_t)b * NPIX * HC;
        __half* ol = g_th_lo + (size_t)b * NPIX * HC;
#pragma unroll
        for (int j = 0; j < 8; j++) {
            int n = n0 + tx * 8 + j;
            __half hs[8], ls[8];
#pragma unroll
            for (int i = 0; i < 8; i++) {
                float v = acc[i][j] + bv[i];
                __half h = __float2half_rn(v);
                hs[i] = h;
                ls[i] = __float2half_rn(v - __half2float(h));
            }
            *(uint4*)&oh[(size_t)n * HC + ty * 8] = *(uint4*)hs;
            if (which == 0)
                *(uint4*)&ol[(size_t)n * HC + ty * 8] = *(uint4*)ls;
        }
    } else {
        __half* ob = g_gh + (size_t)b * HC * NPIX;
#pragma unroll
        for (int i = 0; i < 8; i++) {
            int d = ty * 8 + i;
            __half hv[8];
#pragma unroll
            for (int q = 0; q < 8; q++) hv[q] = __float2half_rn(acc[i][q] + bv[i]);
            *(uint4*)&ob[(size_t)d * NPIX + n0 + tx * 8] = *(uint4*)hv;
        }
    }
}

// ---------------- smem layout for pipelined flash -----------------------------
#define TH_OFF  0u
#define TL_OFF  32768u
#define PH0H    65536u
#define PH1H    98304u
#define G0_OFF  131072u
#define G1_OFF  147456u
#define PP0_OFF 163840u
#define PP1_OFF 180224u
#define HM_OFF  196608u
#define ES_OFF  196608u
#define OSM_OFF 65536u
#define FLASH_SMEM (198656)

// stage a [128 rows][256B] tile (theta), row stride HC halves
__device__ __forceinline__ void stage_full_256(uint32_t dst, const __half* __restrict__ src,
                                               int tid) {
#pragma unroll
    for (int i = 0; i < 8; i++) {
        int id = tid + i * 256;
        int r = id >> 4, c = id & 15;
        CP_ASYNC16(dst + SWZ(r, c), src + (size_t)r * HC + c * 8);
    }
}
// stage a [64 rows][256B] tile (phi half), row stride HC
__device__ __forceinline__ void stage_half_256(uint32_t dst, const __half* __restrict__ src,
                                               int tid) {
#pragma unroll
    for (int i = 0; i < 4; i++) {
        int id = tid + i * 256;
        int r = id >> 4, c = id & 15;
        CP_ASYNC16(dst + SWZ(r, c), src + (size_t)r * HC + c * 8);
    }
}
// stage a [128 rows][128B] tile (g half), row stride NPIX
__device__ __forceinline__ void stage_half_128(uint32_t dst, const __half* __restrict__ src,
                                               int tid) {
#pragma unroll
    for (int i = 0; i < 4; i++) {
        int id = tid + i * 256;
        int r = id >> 3, c = id & 7;
        CP_ASYNC16(dst + SWZP(r, c), src + (size_t)r * NPIX + c * 8);
    }
}

// body macro: H = half index (0..63), PAR = H&1 (literal), SW write sacc, SR read sacc
#define FLASH_BODY(H, PAR, SW, SR) do {                                        \
    if ((H) + 1 < 64) {                                                        \
        const __half* ps = PhH + (size_t)((H) + 1) * 64 * HC;                  \
        stage_half_256(sb + ((PAR) ? PH0H : PH1H), ps, tid);                   \
    }                                                                          \
    stage_half_128(sb + ((PAR) ? G1_OFF : G0_OFF), Gm + (size_t)(H) * 64, tid);\
    CP_COMMIT();                                                               \
    {   /* step1: MMA1(H) = (theta_hi + theta_lo) * phi_hi, interleaved epi(H-1) */ \
        _Pragma("unroll")                                                      \
        for (int tz = 0; tz < 2; tz++)                                         \
            _Pragma("unroll")                                                  \
            for (int jz = 0; jz < 4; jz++)                                     \
                _Pragma("unroll")                                              \
                for (int qz = 0; qz < 4; qz++) SW[tz][jz][qz] = 0.0f;          \
        const uint32_t phh = sb + ((PAR) ? PH1H : PH0H);                       \
        const uint32_t ppb = ((PAR) ? PP0_OFF : PP1_OFF);                      \
        _Pragma("unroll")                                                      \
        for (int kk = 0; kk < 8; kk++) {                                       \
            uint32_t ah[2][4], al[2][4];                                       \
            _Pragma("unroll")                                                  \
            for (int t = 0; t < 2; t++) {                                      \
                int r = wy * 32 + t * 16 + arow;                               \
                int c = 2 * kk + acol;                                         \
                LDSM4(ah[t][0], ah[t][1], ah[t][2], ah[t][3], sb + TH_OFF + SWZ(r, c)); \
                LDSM4(al[t][0], al[t][1], al[t][2], al[t][3], sb + TL_OFF + SWZ(r, c)); \
            }                                                                  \
            _Pragma("unroll")                                                  \
            for (int p = 0; p < 2; p++) {                                      \
                int r = wx * 32 + p * 16 + brow;                               \
                int c = 2 * kk + bcol;                                         \
                uint32_t bh0, bh1, bh2, bh3;                                   \
                LDSM4(bh0, bh1, bh2, bh3, phh + SWZ(r, c));                    \
                _Pragma("unroll")                                              \
                for (int t = 0; t < 2; t++) {                                  \
                    mma16816(SW[t][2 * p],     ah[t], bh0, bh1);               \
                    mma16816(SW[t][2 * p],     al[t], bh0, bh1);               \
                    mma16816(SW[t][2 * p + 1], ah[t], bh2, bh3);               \
                    mma16816(SW[t][2 * p + 1], al[t], bh2, bh3);               \
                }                                                              \
            }                                                                  \
            if ((H) > 0) {  /* epi chunk kk: (t,j) = (kk>>2, kk&3) */          \
                const int te = kk >> 2, je = kk & 3;                           \
                float e0 = fexp(SR[te][je][0] - mcur[te * 2]);                 \
                float e1 = fexp(SR[te][je][1] - mcur[te * 2]);                 \
                float e2 = fexp(SR[te][je][2] - mcur[te * 2 + 1]);             \
                float e3 = fexp(SR[te][je][3] - mcur[te * 2 + 1]);             \
                uint32_t p01 = pack_h2(e0, e1);                                \
                uint32_t p23 = pack_h2(e2, e3);                                \
                __half2 h01 = *reinterpret_cast<__half2*>(&p01);               \
                __half2 h23 = *reinterpret_cast<__half2*>(&p23);               \
                esp[te * 2 + 0] += __low2float(h01) + __high2float(h01);       \
                esp[te * 2 + 1] += __low2float(h23) + __high2float(h23);       \
                int row0 = wy * 32 + te * 16 + (lane >> 2);                    \
                int cch  = wx * 4 + je;                                        \
                *(uint32_t*)(smem + ppb + SWZP(row0, cch) + (lane & 3) * 4)     = p01; \
                *(uint32_t*)(smem + ppb + SWZP(row0 + 8, cch) + (lane & 3) * 4) = p23; \
            }                                                                  \
        }                                                                      \
        /* row max of SW -> HM[PAR] */                                         \
        float mt[4] = {-1e30f, -1e30f, -1e30f, -1e30f};                        \
        _Pragma("unroll")                                                      \
        for (int t = 0; t < 2; t++)                                            \
            _Pragma("unroll")                                                  \
            for (int j = 0; j < 4; j++) {                                      \
                mt[t * 2 + 0] = fmaxf(mt[t * 2 + 0], fmaxf(SW[t][j][0], SW[t][j][1])); \
                mt[t * 2 + 1] = fmaxf(mt[t * 2 + 1], fmaxf(SW[t][j][2], SW[t][j][3])); \
            }                                                                  \
        _Pragma("unroll")                                                      \
        for (int q = 0; q < 4; q++) {                                          \
            mt[q] = fmaxf(mt[q], __shfl_xor_sync(0xFFFFFFFFu, mt[q], 1));      \
            mt[q] = fmaxf(mt[q], __shfl_xor_sync(0xFFFFFFFFu, mt[q], 2));      \
        }                                                                      \
        float* HMp = (float*)(smem + HM_OFF + (PAR) * 1024);                   \
        if ((lane & 3) == 0) {                                                 \
            _Pragma("unroll")                                                  \
            for (int t = 0; t < 2; t++)                                        \
                _Pragma("unroll")                                              \
                for (int h2 = 0; h2 < 2; h2++)                                 \
                    HMp[wx * 128 + wy * 32 + t * 16 + h2 * 8 + (lane >> 2)] = mt[t * 2 + h2]; \
        }                                                                      \
    }                                                                          \
    __syncthreads();                                                           \
    if ((H) > 0) {  /* MMA2(H-1): PP buffer of this parity, g of other parity */ \
        const uint32_t ppb2 = sb + ((PAR) ? PP0_OFF : PP1_OFF);                \
        const uint32_t gb   = sb + ((PAR) ? G0_OFF  : G1_OFF);                 \
        _Pragma("unroll")                                                      \
        for (int kk2 = 0; kk2 < 4; kk2++) {                                    \
            uint32_t ap[2][4];                                                 \
            _Pragma("unroll")                                                  \
            for (int t = 0; t < 2; t++) {                                      \
                int r = wy * 32 + t * 16 + arow;                               \
                LDSM4(ap[t][0], ap[t][1], ap[t][2], ap[t][3],                  \
                      ppb2 + SWZP(r, 2 * kk2 + acol));                         \
            }                                                                  \
            _Pragma("unroll")                                                  \
            for (int p = 0; p < 4; p++) {                                      \
                int r = wx * 64 + p * 16 + brow;                               \
                uint32_t bg0, bg1, bg2, bg3;                                   \
                LDSM4(bg0, bg1, bg2, bg3, gb + SWZP(r, 2 * kk2 + bcol));       \
                _Pragma("unroll")                                              \
                for (int t = 0; t < 2; t++) {                                  \
                    mma16816(oacc[t][2 * p],     ap[t], bg0, bg1);             \
                    mma16816(oacc[t][2 * p + 1], ap[t], bg2, bg3);             \
                }                                                              \
            }                                                                  \
        }                                                                      \
    }                                                                          \
    {   /* rescale(H) from HM[PAR] */                                          \
        float* HMp = (float*)(smem + HM_OFF + (PAR) * 1024);                   \
        float scv[4];                                                          \
        _Pragma("unroll")                                                      \
        for (int t = 0; t < 2; t++)                                            \
            _Pragma("unroll")                                                  \
            for (int h2 = 0; h2 < 2; h2++) {                                   \
                int q = t * 2 + h2;                                            \
                int row = wy * 32 + t * 16 + h2 * 8 + (lane >> 2);             \
                float tm = fmaxf(HMp[row], HMp[128 + row]);                    \
                float Mn = fmaxf(mrun[q], tm);                                 \
                scv[q] = fexp(mrun[q] - Mn);                                   \
                mrun[q] = Mn; mcur[q] = Mn;                                    \
                esp[q] *= scv[q];                                              \
            }                                                                  \
        _Pragma("unroll")                                                      \
        for (int t = 0; t < 2; t++)                                            \
            _Pragma("unroll")                                                  \
            for (int j = 0; j < 8; j++) {                                      \
                oacc[t][j][0] *= scv[t * 2];     oacc[t][j][1] *= scv[t * 2];  \
                oacc[t][j][2] *= scv[t * 2 + 1]; oacc[t][j][3] *= scv[t * 2 + 1]; \
            }                                                                  \
    }                                                                          \
    CP_WAIT0();                                                                \
    __syncthreads();                                                           \
} while (0)

__global__ __launch_bounds__(256, 1) void flash_mma_kernel()
{
    extern __shared__ char smem[];
    const uint32_t sb = smem_to_u32(smem);
    const int tid  = threadIdx.x;
    const int wid  = tid >> 5, lane = tid & 31;
    const int wy   = wid >> 1;          // n band (0..3)
    const int wx   = wid & 1;           // m / d half (0..1)
    const int n0   = blockIdx.x * 128;
    const int b    = blockIdx.y;

    const __half* ThH = g_th_hi + ((size_t)b * NPIX + n0) * HC;
    const __half* ThL = g_th_lo + ((size_t)b * NPIX + n0) * HC;
    const __half* PhH = g_ph_hi + (size_t)b * NPIX * HC;
    const __half* Gm  = g_gh    + (size_t)b * HC * NPIX;
    float*        Yb  = g_y     + (size_t)b * HC * NPIX;

    // prologue: theta hi/lo (resident) + phi(0) hi
    stage_full_256(sb + TH_OFF, ThH, tid);
    stage_full_256(sb + TL_OFF, ThL, tid);
    stage_half_256(sb + PH0H, PhH, tid);
    CP_COMMIT();
    CP_WAIT0();
    __syncthreads();

    float oacc[2][8][4];
#pragma unroll
    for (int t = 0; t < 2; t++)
#pragma unroll
        for (int j = 0; j < 8; j++)
#pragma unroll
            for (int q = 0; q < 4; q++) oacc[t][j][q] = 0.0f;
    float esp[4]  = {0.0f, 0.0f, 0.0f, 0.0f};
    float mrun[4] = {-1e30f, -1e30f, -1e30f, -1e30f};
    float mcur[4] = {-1e30f, -1e30f, -1e30f, -1e30f};
    float sacc0[2][4][4], sacc1[2][4][4];

    const int arow = (lane & 7) + ((lane >> 3) & 1) * 8;
    const int acol = lane >> 4;
    const int brow = (lane & 7) + (lane >> 4) * 8;
    const int bcol = (lane >> 3) & 1;

#pragma unroll 1
    for (int h = 0; h < 64; h += 2) {
        FLASH_BODY(h,     0, sacc0, sacc1);
        FLASH_BODY(h + 1, 1, sacc1, sacc0);
    }

    // tail body (h = 64): epi(63) [reads sacc1, PP1], barrier, MMA2(63)
    {
        const uint32_t ppb = PP1_OFF;
#pragma unroll
        for (int kk = 0; kk < 8; kk++) {
            const int te = kk >> 2, je = kk & 3;
            float e0 = fexp(sacc1[te][je][0] - mcur[te * 2]);
            float e1 = fexp(sacc1[te][je][1] - mcur[te * 2]);
            float e2 = fexp(sacc1[te][je][2] - mcur[te * 2 + 1]);
            float e3 = fexp(sacc1[te][je][3] - mcur[te * 2 + 1]);
            uint32_t p01 = pack_h2(e0, e1);
            uint32_t p23 = pack_h2(e2, e3);
            __half2 h01 = *reinterpret_cast<__half2*>(&p01);
            __half2 h23 = *reinterpret_cast<__half2*>(&p23);
            esp[te * 2 + 0] += __low2float(h01) + __high2float(h01);
            esp[te * 2 + 1] += __low2float(h23) + __high2float(h23);
            int row0 = wy * 32 + te * 16 + (lane >> 2);
            int cch  = wx * 4 + je;
            *(uint32_t*)(smem + ppb + SWZP(row0, cch) + (lane & 3) * 4)     = p01;
            *(uint32_t*)(smem + ppb + SWZP(row0 + 8, cch) + (lane & 3) * 4) = p23;
        }
        __syncthreads();
        const uint32_t ppb2 = sb + PP1_OFF;
        const uint32_t gb   = sb + G1_OFF;
#pragma unroll
        for (int kk2 = 0; kk2 < 4; kk2++) {
            uint32_t ap[2][4];
#pragma unroll
            for (int t = 0; t < 2; t++) {
                int r = wy * 32 + t * 16 + arow;
                LDSM4(ap[t][0], ap[t][1], ap[t][2], ap[t][3],
                      ppb2 + SWZP(r, 2 * kk2 + acol));
            }
#pragma unroll
            for (int p = 0; p < 4; p++) {
                int r = wx * 64 + p * 16 + brow;
                uint32_t bg0, bg1, bg2, bg3;
                LDSM4(bg0, bg1, bg2, bg3, gb + SWZP(r, 2 * kk2 + bcol));
#pragma unroll
                for (int t = 0; t < 2; t++) {
                    mma16816(oacc[t][2 * p],     ap[t], bg0, bg1);
                    mma16816(oacc[t][2 * p + 1], ap[t], bg2, bg3);
                }
            }
        }
        __syncthreads();
    }

    // ---- softmax denominators --------------------------------------------
    float* ES = (float*)(smem + ES_OFF);
#pragma unroll
    for (int q = 0; q < 4; q++) {
        float v = esp[q];
        v += __shfl_xor_sync(0xFFFFFFFFu, v, 1);
        v += __shfl_xor_sync(0xFFFFFFFFu, v, 2);
        if ((lane & 3) == 0)
            ES[wx * 128 + wy * 32 + (q >> 1) * 16 + (q & 1) * 8 + (lane >> 2)] = v;
    }
    __syncthreads();

    // ---- normalize, stage O[n][d] in smem --------------------------------
    float* OSM = (float*)(smem + OSM_OFF);   // [128][132]
#pragma unroll
    for (int t = 0; t < 2; t++) {
        int row0 = wy * 32 + t * 16 + (lane >> 2);
        float rv0 = 1.0f / (ES[row0] + ES[128 + row0]);
        float rv1 = 1.0f / (ES[row0 + 8] + ES[128 + row0 + 8]);
#pragma unroll
        for (int j = 0; j < 8; j++) {
            int d = wx * 64 + j * 8 + (lane & 3) * 2;
            OSM[row0 * 132 + d]           = oacc[t][j][0] * rv0;
            OSM[row0 * 132 + d + 1]       = oacc[t][j][1] * rv0;
            OSM[(row0 + 8) * 132 + d]     = oacc[t][j][2] * rv1;
            OSM[(row0 + 8) * 132 + d + 1] = oacc[t][j][3] * rv1;
        }
    }
    __syncthreads();

    // ---- coalesced y write: y[b][d][n] -----------------------------------
#pragma unroll
    for (int i = 0; i < 16; i++) {
        int id = tid + i * 256;
        int d = id >> 5, nc = (id & 31) * 4;
        float4 v;
        v.x = OSM[(nc + 0) * 132 + d];
        v.y = OSM[(nc + 1) * 132 + d];
        v.z = OSM[(nc + 2) * 132 + d];
        v.w = OSM[(nc + 3) * 132 + d];
        *(float4*)&Yb[(size_t)d * NPIX + n0 + nc] = v;
    }
}

// ---------------- final: z[c][n] = sum_d w_w[c][d] y[d][n] + b_w[c] + x ------
__global__ __launch_bounds__(256) void final_kernel(
    const float* __restrict__ ww, const float* __restrict__ bw,
    const float* __restrict__ x, float* __restrict__ out)
{
    __shared__ float wTs[16][132];
    __shared__ float ys[16][128];
    const int tid = threadIdx.x;
    const int ty = tid >> 4, tx = tid & 15;
    const int wp = tid >> 5, lane = tid & 31;
    const int n0 = blockIdx.x * 128;
    const int c0 = blockIdx.y * 128;
    const int b  = blockIdx.z;
    const float* Yb = g_y + (size_t)b * HC * NPIX;

    float acc[8][8];
#pragma unroll
    for (int i = 0; i < 8; i++)
#pragma unroll
        for (int j = 0; j < 8; j++) acc[i][j] = 0.0f;

    for (int kc = 0; kc < HC; kc += 16) {
        __syncthreads();
#pragma unroll
        for (int s = 0; s < 8; s++) {
            int li = s * 256 + tid;
            int c = li >> 4, dd = li & 15;
            wTs[dd][c] = ww[(size_t)(c0 + c) * HC + kc + dd];
        }
#pragma unroll
        for (int r = wp; r < 16; r += 8)
            *(float4*)&ys[r][lane * 4] =
                *(const float4*)&Yb[(size_t)(kc + r) * NPIX + n0 + lane * 4];
        __syncthreads();
#pragma unroll
        for (int dd = 0; dd < 16; dd++) {
            float a[8], bb[8];
            *(float4*)&a[0]  = *(float4*)&wTs[dd][ty * 8];
            *(float4*)&a[4]  = *(float4*)&wTs[dd][ty * 8 + 4];
            *(float4*)&bb[0] = *(float4*)&ys[dd][tx * 8];
            *(float4*)&bb[4] = *(float4*)&ys[dd][tx * 8 + 4];
#pragma unroll
            for (int i = 0; i < 8; i++)
#pragma unroll
                for (int j = 0; j < 8; j++) acc[i][j] = fmaf(a[i], bb[j], acc[i][j]);
        }
    }

    const float* xb = x + ((size_t)b * CIN + c0) * NPIX;
    float* ob = out + ((size_t)b * CIN + c0) * NPIX;
#pragma unroll
    for (int i = 0; i < 8; i++) {
        int c = ty * 8 + i;
        float bi = bw[c0 + c];
        float4 xv0 = *(const float4*)&xb[(size_t)c * NPIX + n0 + tx * 8];
        float4 xv1 = *(const float4*)&xb[(size_t)c * NPIX + n0 + tx * 8 + 4];
        float4 v0, v1;
        v0.x = acc[i][0] + bi + xv0.x; v0.y = acc[i][1] + bi + xv0.y;
        v0.z = acc[i][2] + bi + xv0.z; v0.w = acc[i][3] + bi + xv0.w;
        v1.x = acc[i][4] + bi + xv1.x; v1.y = acc[i][5] + bi + xv1.y;
        v1.z = acc[i][6] + bi + xv1.z; v1.w = acc[i][7] + bi + xv1.w;
        *(float4*)&ob[(size_t)c * NPIX + n0 + tx * 8]     = v0;
        *(float4*)&ob[(size_t)c * NPIX + n0 + tx * 8 + 4] = v1;
    }
}

// ---------------- launch -----------------------------------------------------
extern "C" void kernel_launch(void* const* d_in, const int* in_sizes, int n_in,
                              void* d_out, int out_size)
{
    const float* x       = (const float*)d_in[0];
    const float* w_theta = (const float*)d_in[1];
    const float* b_theta = (const float*)d_in[2];
    const float* w_phi   = (const float*)d_in[3];
    const float* b_phi   = (const float*)d_in[4];
    const float* w_g     = (const float*)d_in[5];
    const float* b_g     = (const float*)d_in[6];
    const float* w_w     = (const float*)d_in[7];
    const float* b_w     = (const float*)d_in[8];
    float* out = (float*)d_out;

    cudaFuncSetAttribute(flash_mma_kernel,
                         cudaFuncAttributeMaxDynamicSharedMemorySize, FLASH_SMEM);

    dim3 g1(32, BATCH);
    proj_kernel<<<g1, 256>>>(x, w_theta, b_theta, 0);
    proj_kernel<<<g1, 256>>>(x, w_phi,   b_phi,   1);
    proj_kernel<<<g1, 256>>>(x, w_g,     b_g,     2);
    flash_mma_kernel<<<g1, 256, FLASH_SMEM>>>();
    final_kernel<<<dim3(32, 2, BATCH), 256>>>(w_w, b_w, x, out);
}